// round 1
// baseline (speedup 1.0000x reference)
#include <cuda_runtime.h>
#include <cstdint>

// DKD keypoint detection:
//   scores_map (1,1,2048,2048) f32, descriptor_map (1,64,2048,2048) f32
//   -> kpts (1000,2) [x,y], descriptors (1000,64,1) L2-normalized, scores (1000)
// Output assumed packed float32: [kpts(2000) | descriptors(64000) | scores(1000)]

#define HH 2048
#define WW 2048
#define TH 512
#define TW 512
#define NTILES (TH * TW)
#define TOPK 1000
#define CAND_CAP 2048
#define SORT_N 2048

// ---- device scratch (no allocations allowed) ----
__device__ unsigned long long g_keys[NTILES];     // 2 MB
__device__ unsigned int g_hist0[4096];
__device__ unsigned int g_hist1[4096];
__device__ unsigned int g_hist2[256];
__device__ unsigned int g_prefix;
__device__ unsigned int g_remaining;
__device__ unsigned int g_candCount;
__device__ unsigned long long g_cand[CAND_CAP];
__device__ int2 g_sel[TOPK];

// ---------------------------------------------------------------------------
__global__ void reset_kernel() {
    int t = threadIdx.x;  // 1024
    for (int i = t; i < 4096; i += 1024) { g_hist0[i] = 0u; g_hist1[i] = 0u; }
    if (t < 256) g_hist2[t] = 0u;
    if (t == 0) { g_prefix = 0u; g_remaining = TOPK; g_candCount = 0u; }
}

// ---------------------------------------------------------------------------
// One thread per 4x4 tile: border-zeroed max + first-arg, write packed key,
// privatized shared histogram over top 12 bits of the float pattern.
__global__ void tilemax_kernel(const float* __restrict__ s) {
    __shared__ unsigned int sh[4096];
    int lt = threadIdx.x;  // 256
    for (int i = lt; i < 4096; i += 256) sh[i] = 0u;
    __syncthreads();

    int tile = blockIdx.x * 256 + lt;      // 0..262143
    int tr = tile >> 9, tc = tile & 511;
    int r0 = tr << 2, c0 = tc << 2;

    float best = -1.0f;
    int arg = 0;
#pragma unroll
    for (int kr = 0; kr < 4; kr++) {
        int r = r0 + kr;
        bool rok = (r >= 3) && (r < HH - 2);
        float4 v = *reinterpret_cast<const float4*>(s + (size_t)r * WW + c0);
        float f0 = v.x, f1 = v.y, f2 = v.z, f3 = v.w;
        float fv[4] = {f0, f1, f2, f3};
#pragma unroll
        for (int kc = 0; kc < 4; kc++) {
            int c = c0 + kc;
            float val = (rok && c >= 3 && c < WW - 2) ? fv[kc] : 0.0f;
            if (val > best) { best = val; arg = kr * 4 + kc; }  // first max wins
        }
    }
    unsigned int vb = __float_as_uint(best);  // best >= 0 -> monotone bits
    unsigned long long key = ((unsigned long long)vb << 22) |
                             ((unsigned long long)(unsigned)tile << 4) |
                             (unsigned long long)(unsigned)arg;
    g_keys[tile] = key;

    atomicAdd(&sh[vb >> 20], 1u);
    __syncthreads();
    for (int i = lt; i < 4096; i += 256) {
        unsigned int c = sh[i];
        if (c) atomicAdd(&g_hist0[i], c);
    }
}

// ---------------------------------------------------------------------------
// Single-block resolve: scan histogram from the top, find the bucket where the
// cumulative count crosses g_remaining; extend g_prefix by `bits`.
__global__ void resolve_kernel(int stage) {
    __shared__ unsigned int s_hist[4096];
    __shared__ unsigned int s_coarse[256];
    const unsigned int* hist;
    int nb, bits;
    if (stage == 0)      { hist = g_hist0; nb = 4096; bits = 12; }
    else if (stage == 1) { hist = g_hist1; nb = 4096; bits = 12; }
    else                 { hist = g_hist2; nb = 256;  bits = 8;  }

    int t = threadIdx.x;  // 256
    int chunk = nb >> 8;  // 16 or 1
    for (int i = t; i < nb; i += 256) s_hist[i] = hist[i];
    __syncthreads();
    unsigned int sum = 0;
    for (int i = 0; i < chunk; i++) sum += s_hist[t * chunk + i];
    s_coarse[t] = sum;
    __syncthreads();

    if (t == 0) {
        unsigned int R = g_remaining;
        unsigned int cum = 0;
        int ci = 255;
        for (; ci > 0; ci--) {
            if (cum + s_coarse[ci] >= R) break;
            cum += s_coarse[ci];
        }
        int bucket = ci * chunk;
        for (int b = ci * chunk + chunk - 1; b >= ci * chunk; b--) {
            if (cum + s_hist[b] >= R) { bucket = b; break; }
            cum += s_hist[b];
        }
        g_prefix = (g_prefix << bits) | (unsigned int)bucket;
        g_remaining = R - cum;
    }
}

// ---------------------------------------------------------------------------
__global__ void hist1_kernel() {
    __shared__ unsigned int sh[4096];
    int lt = threadIdx.x;  // 512
    for (int i = lt; i < 4096; i += 512) sh[i] = 0u;
    __syncthreads();
    unsigned int pfx = g_prefix;
    int i = blockIdx.x * 512 + lt;
    unsigned int vb = (unsigned int)(g_keys[i] >> 22);
    if ((vb >> 20) == pfx) atomicAdd(&sh[(vb >> 8) & 0xFFFu], 1u);
    __syncthreads();
    for (int j = lt; j < 4096; j += 512) {
        unsigned int c = sh[j];
        if (c) atomicAdd(&g_hist1[j], c);
    }
}

__global__ void hist2_kernel() {
    __shared__ unsigned int sh[256];
    int lt = threadIdx.x;  // 512
    if (lt < 256) sh[lt] = 0u;
    __syncthreads();
    unsigned int pfx = g_prefix;
    int i = blockIdx.x * 512 + lt;
    unsigned int vb = (unsigned int)(g_keys[i] >> 22);
    if ((vb >> 8) == pfx) atomicAdd(&sh[vb & 0xFFu], 1u);
    __syncthreads();
    if (lt < 256) {
        unsigned int c = sh[lt];
        if (c) atomicAdd(&g_hist2[lt], c);
    }
}

// ---------------------------------------------------------------------------
__global__ void gather_kernel() {
    unsigned int T = g_prefix;  // full 32-bit value threshold after stage 2
    int i = blockIdx.x * 512 + threadIdx.x;
    unsigned long long key = g_keys[i];
    unsigned int vb = (unsigned int)(key >> 22);
    if (vb >= T) {
        unsigned int p = atomicAdd(&g_candCount, 1u);
        if (p < CAND_CAP) g_cand[p] = key;
    }
}

// ---------------------------------------------------------------------------
// Single-block bitonic sort (descending) of <=2048 candidates, then emit the
// top-1000 in ascending order (matching argsort semantics exactly: keys are
// (valbits, tileIdx) lexicographic, index breaks ties).
__global__ void sort_emit_kernel(float* __restrict__ out) {
    __shared__ unsigned long long a[SORT_N];
    int t = threadIdx.x;  // 1024
    unsigned int n = g_candCount;
    if (n > CAND_CAP) n = CAND_CAP;
    for (int i = t; i < SORT_N; i += 1024) a[i] = (i < (int)n) ? g_cand[i] : 0ULL;
    __syncthreads();

    for (int k = 2; k <= SORT_N; k <<= 1) {
        for (int j = k >> 1; j > 0; j >>= 1) {
#pragma unroll
            for (int base = 0; base < SORT_N; base += 1024) {
                int i = base + t;
                int ixj = i ^ j;
                if (ixj > i) {
                    unsigned long long x = a[i], y = a[ixj];
                    bool ddd = ((i & k) == 0);  // descending overall
                    if ((x < y) == ddd) { a[i] = y; a[ixj] = x; }
                }
            }
            __syncthreads();
        }
    }

    if (t < TOPK) {
        unsigned long long key = a[t];     // rank t in descending order
        int p = TOPK - 1 - t;              // ascending output position
        unsigned int vb  = (unsigned int)(key >> 22);
        unsigned int idx = (unsigned int)(key >> 4) & 0x3FFFFu;
        unsigned int arg = (unsigned int)key & 0xFu;
        int tr = (int)(idx >> 9), tc = (int)(idx & 511u);
        int row = tr * 4 + (int)(arg >> 2);
        int col = tc * 4 + (int)(arg & 3u);
        out[p * 2 + 0] = (float)col;                       // kpts x
        out[p * 2 + 1] = (float)row;                       // kpts y
        out[2 * TOPK + 64 * TOPK + p] = __uint_as_float(vb);  // scores
        g_sel[p] = make_int2(col, row);
    }
}

// ---------------------------------------------------------------------------
// One block per keypoint, 64 threads = 64 channels. L2-normalize and write.
__global__ void desc_kernel(const float* __restrict__ dmap, float* __restrict__ out) {
    __shared__ float ws[2];
    int p = blockIdx.x;
    int c = threadIdx.x;  // 64
    int2 kp = g_sel[p];
    float v = dmap[(size_t)c * (HH * WW) + (size_t)kp.y * WW + (size_t)kp.x];
    float sq = v * v;
#pragma unroll
    for (int o = 16; o > 0; o >>= 1) sq += __shfl_down_sync(0xFFFFFFFFu, sq, o);
    if ((c & 31) == 0) ws[c >> 5] = sq;
    __syncthreads();
    float inv = rsqrtf(ws[0] + ws[1]);
    out[2 * TOPK + p * 64 + c] = v * inv;
}

// ---------------------------------------------------------------------------
extern "C" void kernel_launch(void* const* d_in, const int* in_sizes, int n_in,
                              void* d_out, int out_size) {
    const float* scores = (const float*)d_in[0];
    const float* dmap   = (const float*)d_in[1];
    // defensive: scores is the smaller tensor (4M vs 268M elements)
    if (n_in >= 2 && in_sizes[0] > in_sizes[1]) {
        const float* tmp = scores; scores = dmap; dmap = tmp;
    }
    float* out = (float*)d_out;

    reset_kernel<<<1, 1024>>>();
    tilemax_kernel<<<NTILES / 256, 256>>>(scores);
    resolve_kernel<<<1, 256>>>(0);
    hist1_kernel<<<NTILES / 512, 512>>>();
    resolve_kernel<<<1, 256>>>(1);
    hist2_kernel<<<NTILES / 512, 512>>>();
    resolve_kernel<<<1, 256>>>(2);
    gather_kernel<<<NTILES / 512, 512>>>();
    sort_emit_kernel<<<1, 1024>>>(out);
    desc_kernel<<<TOPK, 64>>>(dmap, out);
}

// round 2
// speedup vs baseline: 1.7929x; 1.7929x over previous
#include <cuda_runtime.h>
#include <cstdint>

// DKD keypoint detection on (1,1,2048,2048) scores + (1,64,2048,2048) descriptors.
// Output packed float32: [kpts(2000) | descriptors(64000) | scores(1000)]  (verified R1)
//
// Pipeline (4 launches):
//   1. tilemax : per-4x4-tile border-zeroed max -> 64-bit key (valbits<<32|tile<<4|arg),
//                privatized smem histogram over bucket(vb)=min(4095,(1.0f_bits-vb)>>11)
//   2. resolve : find smallest B with cum count >= 1000; zero scratch for next replay
//   3. gather  : keys with bucket<=B -> candidate list (warp-aggregated atomics), ~1k-1.6k
//   4. rank+desc: exact rank by count-of-greater over smem candidates (keys unique),
//                emit kpts/scores ascending, then gather+L2-normalize 64-dim descriptor

#define HH 2048
#define WW 2048
#define NTILES (512 * 512)
#define TOPK 1000
#define CAND_CAP 2048
#define NB 4096
#define ONE_BITS 0x3F800000u

__device__ unsigned long long g_keys[NTILES];   // 2 MB, L2-resident
__device__ unsigned int g_hist[NB];
__device__ unsigned int g_B;
__device__ unsigned int g_candCount;
__device__ unsigned long long g_cand[CAND_CAP];

__device__ __forceinline__ unsigned int bucket_of(unsigned int vb) {
    unsigned int d = ONE_BITS - vb;          // vb in [0, 0x3F7FFFFF] -> d >= 1
    unsigned int b = d >> 11;
    return b > 4095u ? 4095u : b;
}

// ---------------------------------------------------------------------------
__global__ void tilemax_kernel(const float* __restrict__ s) {
    __shared__ unsigned int sh[NB];
    int lt = threadIdx.x;  // 256
#pragma unroll
    for (int i = lt; i < NB; i += 256) sh[i] = 0u;
    __syncthreads();

    int tile = blockIdx.x * 256 + lt;
    int tr = tile >> 9, tc = tile & 511;
    int r0 = tr << 2, c0 = tc << 2;

    float best = -1.0f;
    int arg = 0;
#pragma unroll
    for (int kr = 0; kr < 4; kr++) {
        int r = r0 + kr;
        bool rok = (r >= 3) && (r < HH - 2);
        float4 v = *reinterpret_cast<const float4*>(s + (size_t)r * WW + c0);
        float fv[4] = {v.x, v.y, v.z, v.w};
#pragma unroll
        for (int kc = 0; kc < 4; kc++) {
            int c = c0 + kc;
            float val = (rok && c >= 3 && c < WW - 2) ? fv[kc] : 0.0f;
            if (val > best) { best = val; arg = kr * 4 + kc; }  // first max wins
        }
    }
    unsigned int vb = __float_as_uint(best);  // non-negative -> monotone bit pattern
    g_keys[tile] = ((unsigned long long)vb << 32) |
                   ((unsigned long long)((unsigned)tile << 4)) |
                   (unsigned long long)(unsigned)arg;

    atomicAdd(&sh[bucket_of(vb)], 1u);
    __syncthreads();
    for (int i = lt; i < NB; i += 256) {
        unsigned int c = sh[i];
        if (c) atomicAdd(&g_hist[i], c);
    }
}

// ---------------------------------------------------------------------------
// Single block, 1024 threads. Find smallest B with sum(hist[0..B]) >= TOPK.
// Also restores scratch (hist, candCount) to zero for the next graph replay.
__global__ void resolve_kernel() {
    __shared__ unsigned int s_hist[NB];      // 16 KB
    __shared__ unsigned int part[1024];      // per-thread sum of its 4 buckets
    __shared__ unsigned int wsum[32];
    int t = threadIdx.x;

    unsigned int h0 = g_hist[t * 4 + 0];
    unsigned int h1 = g_hist[t * 4 + 1];
    unsigned int h2 = g_hist[t * 4 + 2];
    unsigned int h3 = g_hist[t * 4 + 3];
    s_hist[t * 4 + 0] = h0; s_hist[t * 4 + 1] = h1;
    s_hist[t * 4 + 2] = h2; s_hist[t * 4 + 3] = h3;
    unsigned int ps = h0 + h1 + h2 + h3;
    part[t] = ps;

    // zero global scratch for next replay (values already captured in smem)
    g_hist[t * 4 + 0] = 0u; g_hist[t * 4 + 1] = 0u;
    g_hist[t * 4 + 2] = 0u; g_hist[t * 4 + 3] = 0u;
    if (t == 0) g_candCount = 0u;

    // warp-level sums of 128-bucket spans
    unsigned int ws = ps;
#pragma unroll
    for (int o = 16; o > 0; o >>= 1) ws += __shfl_down_sync(0xFFFFFFFFu, ws, o);
    if ((t & 31) == 0) wsum[t >> 5] = ws;
    __syncthreads();

    if (t == 0) {
        unsigned int cum = 0;
        int w = 0;
        for (; w < 31; w++) { if (cum + wsum[w] >= TOPK) break; cum += wsum[w]; }
        int tt = w * 32;
        for (; tt < w * 32 + 31; tt++) { if (cum + part[tt] >= TOPK) break; cum += part[tt]; }
        int B = tt * 4;
        for (int b = tt * 4; b < tt * 4 + 4; b++) {
            if (cum + s_hist[b] >= TOPK) { B = b; break; }
            cum += s_hist[b];
        }
        g_B = (unsigned int)B;
    }
}

// ---------------------------------------------------------------------------
__global__ void gather_kernel() {
    unsigned int B = g_B;
    int base = blockIdx.x * 1024 + threadIdx.x;  // 256 blocks x 256 threads, 4 keys each
    int lane = threadIdx.x & 31;
#pragma unroll
    for (int k = 0; k < 4; k++) {
        int i = base + k * 256;
        unsigned long long key = g_keys[i];
        unsigned int vb = (unsigned int)(key >> 32);
        bool pred = (bucket_of(vb) <= B);
        unsigned int mask = __ballot_sync(0xFFFFFFFFu, pred);
        if (mask) {
            unsigned int pos = 0;
            int leader = __ffs(mask) - 1;
            if (lane == leader) pos = atomicAdd(&g_candCount, (unsigned)__popc(mask));
            pos = __shfl_sync(0xFFFFFFFFu, pos, leader);
            if (pred) {
                unsigned int p = pos + __popc(mask & ((1u << lane) - 1u));
                if (p < CAND_CAP) g_cand[p] = key;
            }
        }
    }
}

// ---------------------------------------------------------------------------
// 32 blocks x 64 threads. Each block caches all candidates in smem; thread gi
// computes exact rank of candidate gi (count of greater keys; keys unique),
// emits kpt/score if rank < TOPK, then gathers + normalizes its descriptor.
__global__ void __launch_bounds__(64) rank_desc_kernel(const float* __restrict__ dmap,
                                                       float* __restrict__ out) {
    __shared__ unsigned long long cand[CAND_CAP];  // 16 KB
    int lt = threadIdx.x;
    unsigned int n = g_candCount;
    if (n > CAND_CAP) n = CAND_CAP;
    for (unsigned int i = lt; i < n; i += 64) cand[i] = g_cand[i];
    __syncthreads();  // last barrier; early returns below are safe

    unsigned int gi = blockIdx.x * 64 + lt;
    if (gi >= n) return;
    unsigned long long mykey = cand[gi];

    unsigned int rank = 0;
    unsigned int j = 0;
    for (; j + 4 <= n; j += 4) {
        rank += (cand[j] > mykey);
        rank += (cand[j + 1] > mykey);
        rank += (cand[j + 2] > mykey);
        rank += (cand[j + 3] > mykey);
    }
    for (; j < n; j++) rank += (cand[j] > mykey);
    if (rank >= TOPK) return;

    int p = TOPK - 1 - (int)rank;  // ascending output order (argsort semantics)
    unsigned int vb = (unsigned int)(mykey >> 32);
    unsigned int lo = (unsigned int)mykey;
    unsigned int tile = (lo >> 4) & 0x3FFFFu;
    unsigned int arg = lo & 0xFu;
    int row = (int)(tile >> 9) * 4 + (int)(arg >> 2);
    int col = (int)(tile & 511u) * 4 + (int)(arg & 3u);

    out[p * 2 + 0] = (float)col;
    out[p * 2 + 1] = (float)row;
    out[2 * TOPK + 64 * TOPK + p] = __uint_as_float(vb);

    // descriptor: 64 channels, stride 4M floats; high MLP, then normalize
    const float* base = dmap + (size_t)row * WW + col;
    float v[64];
    float s0 = 0.f, s1 = 0.f, s2 = 0.f, s3 = 0.f;
#pragma unroll
    for (int c = 0; c < 64; c += 4) {
        v[c + 0] = base[(size_t)(c + 0) * (HH * WW)];
        v[c + 1] = base[(size_t)(c + 1) * (HH * WW)];
        v[c + 2] = base[(size_t)(c + 2) * (HH * WW)];
        v[c + 3] = base[(size_t)(c + 3) * (HH * WW)];
        s0 += v[c + 0] * v[c + 0];
        s1 += v[c + 1] * v[c + 1];
        s2 += v[c + 2] * v[c + 2];
        s3 += v[c + 3] * v[c + 3];
    }
    float inv = rsqrtf((s0 + s1) + (s2 + s3));
    float* o = out + 2 * TOPK + p * 64;
#pragma unroll
    for (int c = 0; c < 64; c += 4) {
        float4 w = make_float4(v[c] * inv, v[c + 1] * inv, v[c + 2] * inv, v[c + 3] * inv);
        *reinterpret_cast<float4*>(o + c) = w;
    }
}

// ---------------------------------------------------------------------------
extern "C" void kernel_launch(void* const* d_in, const int* in_sizes, int n_in,
                              void* d_out, int out_size) {
    const float* scores = (const float*)d_in[0];
    const float* dmap   = (const float*)d_in[1];
    if (n_in >= 2 && in_sizes[0] > in_sizes[1]) {  // scores is the smaller tensor
        const float* tmp = scores; scores = dmap; dmap = tmp;
    }
    float* out = (float*)d_out;

    tilemax_kernel<<<NTILES / 256, 256>>>(scores);
    resolve_kernel<<<1, 1024>>>();
    gather_kernel<<<NTILES / 1024, 256>>>();
    rank_desc_kernel<<<32, 64>>>(dmap, out);
}